// round 16
// baseline (speedup 1.0000x reference)
#include <cuda_runtime.h>
#include <cuda_bf16.h>
#include <math.h>
#include <stdint.h>

// ReDrafterHead via mma.sync bf16 (HMMA), multi-kernel + PDL.
// B=64, D=512, H=4096, V=32000, K=4. Exact 2-way bf16 split, 3 cross products
// (a0w0+a0w1+a1w0), fp32 accum.
// R16 = R13 + in-loop GD_WAITs replaced by producer-counter acquire-spins
// (monotonic, replay-safe via per-replay generation g_rep). gh(t) waits only
// combine0(t-1)-done -> overlaps gru1/logits of the previous step.

#define B_ 64
#define D_ 512
#define H_ 4096
#define V_ 32000
#define G3 1536
#define LDOUT 128000L
#define NTILES_V 250

#define STAGE_BYTES 30720        // A0(5120)+A1(5120)+W0(10240)+W1(10240)
#define NSTAGE 3
#define DYN_SMEM (STAGE_BYTES * NSTAGE)

#define GD_TRIGGER() asm volatile("griddepcontrol.launch_dependents;" ::: "memory")
#define GD_WAIT()    asm volatile("griddepcontrol.wait;" ::: "memory")

// phase slots per step: 0=gru0 done, 1=combine0 done, 2=gru1 done,
// 3=combine1 done, 4=logits done
#define SLOT(t, ph) ((t) * 5 + (ph))

// ------------------------------ device scratch ------------------------------
__device__ __align__(128) __nv_bfloat16 g_wo0[V_ * D_],  g_wo1[V_ * D_];
__device__ __align__(128) __nv_bfloat16 g_wi00[G3 * D_], g_wi01[G3 * D_];
__device__ __align__(128) __nv_bfloat16 g_wh00[G3 * D_], g_wh01[G3 * D_];
__device__ __align__(128) __nv_bfloat16 g_wi10[G3 * D_], g_wi11[G3 * D_];
__device__ __align__(128) __nv_bfloat16 g_wh10[G3 * D_], g_wh11[G3 * D_];
__device__ __align__(128) __nv_bfloat16 g_ip0[D_ * H_],  g_ip1[D_ * H_];
__device__ __align__(128) __nv_bfloat16 g_hid0[B_ * H_], g_hid1[B_ * H_];
__device__ __align__(128) __nv_bfloat16 g_h00[B_ * D_],  g_h01[B_ * D_];
__device__ __align__(128) __nv_bfloat16 g_h10[B_ * D_],  g_h11[B_ * D_];
__device__ __align__(128) float g_h0f[B_ * D_];
__device__ __align__(128) float g_h1f[B_ * D_];
__device__ __align__(128) float g_ipart[16 * B_ * D_];
__device__ __align__(128) float g_gP0[8 * B_ * 2 * G3];   // layer0 gate partials
__device__ __align__(128) float g_gP1[8 * B_ * 2 * G3];   // layer1 gate partials
__device__ unsigned long long g_best[B_];                 // packed argmax keys
__device__ unsigned g_rep;                                // replay generation
__device__ unsigned g_ctr[24];                            // monotonic phase ctrs

// ------------------------------ helpers -------------------------------------
__device__ __forceinline__ uint32_t smem_u32(const void* p) {
    uint32_t a;
    asm("{ .reg .u64 t; cvta.to.shared.u64 t, %1; cvt.u32.u64 %0, t; }" : "=r"(a) : "l"(p));
    return a;
}
__device__ __forceinline__ unsigned rep_now() {
    unsigned r;
    asm volatile("ld.global.cg.u32 %0, [%1];" : "=r"(r) : "l"(&g_rep));
    return r;
}
// consumer: block-wide wait until g_ctr[slot] >= target
__device__ __forceinline__ void spin_slot(int slot, unsigned target) {
    if (threadIdx.x == 0) {
        unsigned r;
        for (;;) {
            asm volatile("ld.global.acquire.gpu.u32 %0, [%1];"
                         : "=r"(r) : "l"(&g_ctr[slot]));
            if ((int)(r - target) >= 0) break;
            __nanosleep(64);
        }
    }
    __syncthreads();
}
// producer: all threads' stores -> fence -> one arrival
__device__ __forceinline__ void bump_slot(int slot) {
    __threadfence();
    __syncthreads();
    if (threadIdx.x == 0) atomicAdd(&g_ctr[slot], 1u);
}
__device__ __forceinline__ void cp16(uint32_t dst, const void* src) {
    asm volatile("cp.async.cg.shared.global [%0], [%1], 16;" :: "r"(dst), "l"(src));
}
__device__ __forceinline__ void ldsm4(uint32_t* r, uint32_t a) {
    asm volatile("ldmatrix.sync.aligned.m8n8.x4.shared.b16 {%0,%1,%2,%3}, [%4];"
                 : "=r"(r[0]), "=r"(r[1]), "=r"(r[2]), "=r"(r[3]) : "r"(a));
}
__device__ __forceinline__ void mma16816(float* c, const uint32_t* a,
                                         uint32_t b0, uint32_t b1) {
    asm volatile(
        "mma.sync.aligned.m16n8k16.row.col.f32.bf16.bf16.f32 "
        "{%0,%1,%2,%3}, {%4,%5,%6,%7}, {%8,%9}, {%0,%1,%2,%3};"
        : "+f"(c[0]), "+f"(c[1]), "+f"(c[2]), "+f"(c[3])
        : "r"(a[0]), "r"(a[1]), "r"(a[2]), "r"(a[3]), "r"(b0), "r"(b1));
}
__device__ __forceinline__ void st2cs(float* p, float x, float y) {
    asm volatile("st.global.cs.v2.f32 [%0], {%1, %2};" :: "l"(p), "f"(x), "f"(y)
                 : "memory");
}
__device__ __forceinline__ void split_store4(float4 v, __nv_bfloat16* d0,
                                             __nv_bfloat16* d1, long o)
{
    __nv_bfloat16 h0 = __float2bfloat16(v.x), h1 = __float2bfloat16(v.y);
    __nv_bfloat16 h2 = __float2bfloat16(v.z), h3 = __float2bfloat16(v.w);
    __nv_bfloat162 ha, hb, la, lb;
    ha.x = h0; ha.y = h1; hb.x = h2; hb.y = h3;
    la.x = __float2bfloat16(v.x - __bfloat162float(h0));
    la.y = __float2bfloat16(v.y - __bfloat162float(h1));
    lb.x = __float2bfloat16(v.z - __bfloat162float(h2));
    lb.y = __float2bfloat16(v.w - __bfloat162float(h3));
    *(__nv_bfloat162*)(d0 + o)     = ha;
    *(__nv_bfloat162*)(d0 + o + 2) = hb;
    *(__nv_bfloat162*)(d1 + o)     = la;
    *(__nv_bfloat162*)(d1 + o + 2) = lb;
}
__device__ __forceinline__ void add4(float4& a, float4 b) {
    a.x += b.x; a.y += b.y; a.z += b.z; a.w += b.w;
}

// file-scope stage loaders (use threadIdx.x)
#define LOAD_A_G(sb_, A0p, A1p, lda, kb) do {                                  \
    _Pragma("unroll")                                                          \
    for (int j_ = 0; j_ < 2; j_++) {                                           \
        int q_ = threadIdx.x + j_ * 256;                                       \
        int sp_ = q_ >> 8, rem_ = q_ & 255;                                    \
        int row_ = rem_ >> 2, kc_ = rem_ & 3;                                  \
        cp16((sb_) + (uint32_t)sp_ * 5120u + (uint32_t)row_ * 80u              \
                 + (uint32_t)kc_ * 16u,                                        \
             (sp_ ? (A1p) : (A0p)) + (long)row_ * (lda) + (kb) + kc_ * 8);     \
    }                                                                          \
} while (0)

#define LOAD_W_G(sb_, W0p, W1p, ldw, kb) do {                                  \
    _Pragma("unroll")                                                          \
    for (int j_ = 0; j_ < 4; j_++) {                                           \
        int qq_ = threadIdx.x + j_ * 256;                                      \
        int sp_ = qq_ >> 9, rem_ = qq_ & 511;                                  \
        int row_ = rem_ >> 2, kc_ = rem_ & 3;                                  \
        cp16((sb_) + 10240u + (uint32_t)sp_ * 10240u                           \
                 + (uint32_t)row_ * 80u + (uint32_t)kc_ * 16u,                 \
             (sp_ ? (W1p) : (W0p)) + (long)row_ * (ldw) + (kb) + kc_ * 8);     \
    }                                                                          \
} while (0)

#define COMMIT_G() asm volatile("cp.async.commit_group;" ::: "memory")

// 32-K-chunk compute on the 80B-padded stage layout
__device__ __forceinline__ void compute32(uint32_t sb, float acc[2][4][4],
                                          int lane, int wm, int wn)
{
    uint32_t A0b = sb, A1b = sb + 5120u, W0b = sb + 10240u, W1b = sb + 20480u;
    const int l8 = lane & 7, sel = lane >> 3;
    const uint32_t a_row = (uint32_t)((sel & 1) * 8 + l8);
    const uint32_t a_k8  = (uint32_t)((sel >> 1) * 8);
    const uint32_t b_n   = (uint32_t)(((sel >> 1) ? 8 : 0) + l8);
    const uint32_t b_k8  = (uint32_t)((sel & 1) * 8);
#pragma unroll
    for (int ko = 0; ko < 32; ko += 16) {
        uint32_t a0r[2][4], a1r[2][4], w0r[2][4], w1r[2][4];
#pragma unroll
        for (int mt = 0; mt < 2; mt++) {
            uint32_t ar = (uint32_t)(wm + mt * 16 + a_row) * 80u + (ko + a_k8) * 2u;
            ldsm4(a0r[mt], A0b + ar);
            ldsm4(a1r[mt], A1b + ar);
        }
#pragma unroll
        for (int np = 0; np < 2; np++) {
            uint32_t br = (uint32_t)(wn + np * 16 + b_n) * 80u + (ko + b_k8) * 2u;
            ldsm4(w0r[np], W0b + br);
            ldsm4(w1r[np], W1b + br);
        }
#pragma unroll
        for (int mt = 0; mt < 2; mt++)
#pragma unroll
            for (int nt = 0; nt < 4; nt++)
                mma16816(acc[mt][nt], a0r[mt],
                         w0r[nt >> 1][(nt & 1) * 2], w0r[nt >> 1][(nt & 1) * 2 + 1]);
#pragma unroll
        for (int mt = 0; mt < 2; mt++)
#pragma unroll
            for (int nt = 0; nt < 4; nt++)
                mma16816(acc[mt][nt], a0r[mt],
                         w1r[nt >> 1][(nt & 1) * 2], w1r[nt >> 1][(nt & 1) * 2 + 1]);
#pragma unroll
        for (int mt = 0; mt < 2; mt++)
#pragma unroll
            for (int nt = 0; nt < 4; nt++)
                mma16816(acc[mt][nt], a1r[mt],
                         w0r[nt >> 1][(nt & 1) * 2], w0r[nt >> 1][(nt & 1) * 2 + 1]);
    }
}

__device__ __forceinline__ void store_acc(float acc[2][4][4], float* C, long ldc,
                                          int lane, int wm, int wn)
{
    const int row0 = wm + (lane >> 2);
    const int col0 = wn + (lane & 3) * 2;
#pragma unroll
    for (int mt = 0; mt < 2; mt++)
#pragma unroll
        for (int nt = 0; nt < 4; nt++) {
            float* p = C + (long)(row0 + mt * 16) * ldc + col0 + nt * 8;
            *(float2*)p = make_float2(acc[mt][nt][0], acc[mt][nt][1]);
            float* p2 = p + 8 * ldc;
            *(float2*)p2 = make_float2(acc[mt][nt][2], acc[mt][nt][3]);
        }
}

// ------------------------------ staged GEMM ---------------------------------
// pdl: 1 = W stages 0/1 prefetched BEFORE the dependency point; 2 = dep first.
// wslot >= 0: dependency = spin on g_ctr[wslot] >= wtarget; else GD_WAIT.
__device__ __forceinline__ void hgemm_64x128(
    const __nv_bfloat16* __restrict__ A0, const __nv_bfloat16* __restrict__ A1, int lda,
    const __nv_bfloat16* __restrict__ W0, const __nv_bfloat16* __restrict__ W1, int ldw,
    float* __restrict__ C, long ldc, int klo, int nchunk,
    int pdl, int wslot, unsigned wtarget, bool streamc, int tile, int n0)
{
    extern __shared__ __align__(16) char dynsm[];
    __shared__ float sv[4][64];
    __shared__ int   si[4][64];
    uint32_t sbase = smem_u32(dynsm);
    const int t = threadIdx.x;
    const int lane = t & 31, wid = t >> 5;
    const int wm = (wid & 1) * 32, wn = (wid >> 1) * 32;

    float acc[2][4][4];
#pragma unroll
    for (int i = 0; i < 2; i++)
#pragma unroll
        for (int j = 0; j < 4; j++)
#pragma unroll
            for (int q = 0; q < 4; q++) acc[i][j][q] = 0.f;

    uint32_t sb0 = sbase, sb1 = sbase + STAGE_BYTES;
    if (pdl == 1) {
        LOAD_W_G(sb0, W0, W1, ldw, klo);
        if (nchunk > 1) LOAD_W_G(sb1, W0, W1, ldw, klo + 32);
        if (wslot >= 0) spin_slot(wslot, wtarget); else GD_WAIT();
        LOAD_A_G(sb0, A0, A1, lda, klo);
        COMMIT_G();                       // group0 = {W0, W1, A0}
        if (nchunk > 1) { LOAD_A_G(sb1, A0, A1, lda, klo + 32); COMMIT_G(); }
    } else {
        if (wslot >= 0) spin_slot(wslot, wtarget); else GD_WAIT();
        LOAD_A_G(sb0, A0, A1, lda, klo); LOAD_W_G(sb0, W0, W1, ldw, klo); COMMIT_G();
        if (nchunk > 1) {
            LOAD_A_G(sb1, A0, A1, lda, klo + 32);
            LOAD_W_G(sb1, W0, W1, ldw, klo + 32);
            COMMIT_G();
        }
    }

    for (int s = 0; s < nchunk; s++) {
        if (s + 1 < nchunk) asm volatile("cp.async.wait_group 1;" ::: "memory");
        else                asm volatile("cp.async.wait_group 0;" ::: "memory");
        __syncthreads();
        if (s + 2 < nchunk) {
            int kb2 = klo + (s + 2) * 32;
            uint32_t sb2 = sbase + (uint32_t)((s + 2) % NSTAGE) * STAGE_BYTES;
            LOAD_A_G(sb2, A0, A1, lda, kb2);
            LOAD_W_G(sb2, W0, W1, ldw, kb2);
            COMMIT_G();
        }
        compute32(sbase + (uint32_t)(s % NSTAGE) * STAGE_BYTES, acc, lane, wm, wn);
        __syncthreads();
    }

    if (!streamc) {
        store_acc(acc, C, ldc, lane, wm, wn);
    } else {
        const int row0 = wm + (lane >> 2);
        const int col0 = wn + (lane & 3) * 2;
#pragma unroll
        for (int mt = 0; mt < 2; mt++)
#pragma unroll
            for (int nt = 0; nt < 4; nt++) {
                float* p = C + (long)(row0 + mt * 16) * ldc + col0 + nt * 8;
                st2cs(p,  acc[mt][nt][0], acc[mt][nt][1]);
                st2cs(p + 8 * ldc, acc[mt][nt][2], acc[mt][nt][3]);
            }
    }

    if (tile >= 0) {
        // per-row argmax over this tile's 128 cols -> packed atomic key
#pragma unroll
        for (int mt = 0; mt < 2; mt++)
#pragma unroll
            for (int h = 0; h < 2; h++) {
                float bv = -3.4e38f;
                int bi = 0x7FFFFFFF;
#pragma unroll
                for (int nt = 0; nt < 4; nt++) {
                    int cc = wn + nt * 8 + (lane & 3) * 2;
                    float v0 = acc[mt][nt][h * 2];
                    float v1 = acc[mt][nt][h * 2 + 1];
                    if (v0 > bv || (v0 == bv && cc < bi))     { bv = v0; bi = cc; }
                    if (v1 > bv || (v1 == bv && cc + 1 < bi)) { bv = v1; bi = cc + 1; }
                }
#pragma unroll
                for (int off = 1; off <= 2; off <<= 1) {
                    float ov = __shfl_xor_sync(0xFFFFFFFF, bv, off);
                    int   oi = __shfl_xor_sync(0xFFFFFFFF, bi, off);
                    if (ov > bv || (ov == bv && oi < bi)) { bv = ov; bi = oi; }
                }
                if ((lane & 3) == 0) {
                    int r = wm + mt * 16 + (lane >> 2) + h * 8;
                    sv[wid >> 1][r] = bv;
                    si[wid >> 1][r] = bi;
                }
            }
        __syncthreads();
        if (t < 64) {
            float bv = sv[0][t];
            int bi = si[0][t];
#pragma unroll
            for (int g = 1; g < 4; g++) {
                float v = sv[g][t];
                int i = si[g][t];
                if (v > bv || (v == bv && i < bi)) { bv = v; bi = i; }
            }
            int gidx = n0 + bi;
            uint32_t fu = __float_as_uint(bv);
            fu = (fu & 0x80000000u) ? ~fu : (fu | 0x80000000u);
            unsigned long long key = ((unsigned long long)fu << 32)
                                   | (unsigned long long)(0xFFFFFFFFu - (uint32_t)gidx);
            atomicMax(&g_best[t], key);
        }
        __syncthreads();
    }
}

// ------------------------------ kernels -------------------------------------
__global__ void __launch_bounds__(256) k_split_wo(const float* __restrict__ outw)
{
    const long G4 = (long)V_ * D_ / 4;
    const long stride = 96L * 256L;
    for (long g = (long)blockIdx.x * 256 + threadIdx.x; g < G4; g += stride * 8) {
        float4 v[8];
#pragma unroll
        for (int j = 0; j < 8; j++) {
            long q = g + (long)j * stride;
            if (q < G4) v[j] = *((const float4*)outw + q);
        }
#pragma unroll
        for (int j = 0; j < 8; j++) {
            long q = g + (long)j * stride;
            if (q < G4) split_store4(v[j], g_wo0, g_wo1, q * 4);
        }
    }
}

#define R1 786432L
#define R2 1572864L
#define R3 2359296L
#define R4 3145728L
#define R5 5242880L
#define R6 5505024L
__global__ void __launch_bounds__(256) k_split_rest(
    const float* __restrict__ wih0, const float* __restrict__ whh0,
    const float* __restrict__ wih1, const float* __restrict__ whh1,
    const float* __restrict__ ipw,  const float* __restrict__ hid)
{
    if (blockIdx.x == 0 && threadIdx.x == 0) atomicAdd(&g_rep, 1u);
    long e = ((long)blockIdx.x * 256 + threadIdx.x) * 4;
    if (e >= R6) return;
    const float* s;
    __nv_bfloat16 *d0, *d1;
    long o;
    if (e < R1)      { s = wih0; d0 = g_wi00; d1 = g_wi01; o = e; }
    else if (e < R2) { s = whh0; d0 = g_wh00; d1 = g_wh01; o = e - R1; }
    else if (e < R3) { s = wih1; d0 = g_wi10; d1 = g_wi11; o = e - R2; }
    else if (e < R4) { s = whh1; d0 = g_wh10; d1 = g_wh11; o = e - R3; }
    else if (e < R5) { s = ipw;  d0 = g_ip0;  d1 = g_ip1;  o = e - R4; }
    else             { s = hid;  d0 = g_hid0; d1 = g_hid1; o = e - R5; }
    float4 v = *(const float4*)(s + o);
    split_store4(v, d0, d1, o);
}

__global__ void __launch_bounds__(256) k_inproj(void)
{
    GD_TRIGGER();
    int n0 = blockIdx.x * 128;
    int sp = blockIdx.y;
    hgemm_64x128(g_hid0, g_hid1, H_,
                 g_ip0 + (long)n0 * H_, g_ip1 + (long)n0 * H_, H_,
                 g_ipart + (long)sp * (B_ * D_) + n0, (long)D_, sp * 256, 8,
                 2, -1, 0, false, -1, 0);
}

__global__ void __launch_bounds__(256) k_reduce(const float* __restrict__ bias)
{
    GD_TRIGGER();
    GD_WAIT();
    int idx = (blockIdx.x * 256 + threadIdx.x) * 4;
    int d = idx & (D_ - 1);
    float4 s = *(const float4*)(bias + d);
#pragma unroll
    for (int sp = 0; sp < 16; sp++)
        add4(s, *(const float4*)(g_ipart + sp * (B_ * D_) + idx));
    *(float4*)(g_h0f + idx) = s;
    *(float4*)(g_h1f + idx) = s;
    split_store4(s, g_h00, g_h01, idx);
    split_store4(s, g_h10, g_h11, idx);
}

// Layer0 GRU: step 0 -> grid (12,8), gh tiles only (x = 0), GD_WAIT dep.
// steps 1..3 -> grid (24,8): tiles 0-11 gi (select+gather, waits logits(t-1)),
// tiles 12-23 gh (waits combine0(t-1) only -> overlaps previous step's tail).
__global__ void __launch_bounds__(256) k_gru0(int step, const float* __restrict__ emb)
{
    GD_TRIGGER();
    unsigned R = rep_now();
    int sp = blockIdx.y;
    if (step == 0) {
        int j0 = (blockIdx.x + 12) * 128;
        hgemm_64x128(g_h00, g_h01, D_,
                     g_wh00 + (long)(j0 - G3) * D_, g_wh01 + (long)(j0 - G3) * D_, D_,
                     g_gP0 + (long)sp * (B_ * 2 * G3) + j0, (long)(2 * G3), sp * 64, 2,
                     1, -1, 0, false, -1, 0);
        bump_slot(SLOT(0, 0));
        return;
    }

    int tile = blockIdx.x;
    int klo = sp * 64;
    if (tile >= 12) {
        // gh half: depends only on combine0(step-1)
        int j0 = tile * 128;
        hgemm_64x128(g_h00, g_h01, D_,
                     g_wh00 + (long)(j0 - G3) * D_, g_wh01 + (long)(j0 - G3) * D_, D_,
                     g_gP0 + (long)sp * (B_ * 2 * G3) + j0, (long)(2 * G3), klo, 2,
                     1, SLOT(step - 1, 1), R * 32u, false, -1, 0);
        bump_slot(SLOT(step, 0));
        return;
    }

    // gi half: depends on logits(step-1) candidates
    int j0 = tile * 128;
    extern __shared__ __align__(16) char dynsm[];
    __shared__ int win[64];
    uint32_t sbase = smem_u32(dynsm);
    const int t = threadIdx.x, lane = t & 31, wid = t >> 5;
    const int wm = (wid & 1) * 32, wn = (wid >> 1) * 32;
    const __nv_bfloat16* W0 = g_wi00 + (long)j0 * D_;
    const __nv_bfloat16* W1 = g_wi01 + (long)j0 * D_;
    uint32_t sb0 = sbase, sb1 = sbase + STAGE_BYTES;

    LOAD_W_G(sb0, W0, W1, D_, klo); COMMIT_G();        // group0
    LOAD_W_G(sb1, W0, W1, D_, klo + 32); COMMIT_G();   // group1
    spin_slot(SLOT(step - 1, 4), R * (unsigned)NTILES_V);

    if (t < 64) {
        unsigned long long v = g_best[t];
        win[t] = (int)(0xFFFFFFFFu - (uint32_t)(v & 0xFFFFFFFFull));
    }
    __syncthreads();

    {
        int r = t >> 2, c0 = (t & 3) * 16;
        const float* erow = emb + (long)win[r] * D_ + klo;
#pragma unroll
        for (int cc = 0; cc < 16; cc += 4) {
            float4 v4 = *(const float4*)(erow + c0 + cc);
            float vv[4] = {v4.x, v4.y, v4.z, v4.w};
#pragma unroll
            for (int i = 0; i < 4; i++) {
                int k = c0 + cc + i;
                uint32_t sb = (k >= 32) ? sb1 : sb0;
                int kk = k & 31;
                uint32_t off = (uint32_t)r * 80u + (uint32_t)(kk >> 3) * 16u
                             + (uint32_t)(kk & 7) * 2u;
                __nv_bfloat16 hi = __float2bfloat16(vv[i]);
                __nv_bfloat16 lo = __float2bfloat16(vv[i] - __bfloat162float(hi));
                *(__nv_bfloat16*)(dynsm + (sb - sbase) + off) = hi;
                *(__nv_bfloat16*)(dynsm + (sb - sbase) + 5120u + off) = lo;
            }
        }
    }

    float acc[2][4][4];
#pragma unroll
    for (int i = 0; i < 2; i++)
#pragma unroll
        for (int j = 0; j < 4; j++)
#pragma unroll
            for (int q = 0; q < 4; q++) acc[i][j][q] = 0.f;

    asm volatile("cp.async.wait_group 1;" ::: "memory");
    __syncthreads();                 // A smem stores + W group0 visible
    compute32(sb0, acc, lane, wm, wn);
    asm volatile("cp.async.wait_group 0;" ::: "memory");
    __syncthreads();
    compute32(sb1, acc, lane, wm, wn);

    store_acc(acc, g_gP0 + (long)sp * (B_ * 2 * G3) + j0, (long)(2 * G3),
              lane, wm, wn);
    bump_slot(SLOT(step, 0));
}

__global__ void __launch_bounds__(256) k_gru1(int step)
{
    GD_TRIGGER();
    unsigned R = rep_now();
    int tile = blockIdx.x;
    int sp = blockIdx.y;
    int j0 = tile * 128;
    const __nv_bfloat16 *A0, *A1, *W0, *W1;
    if (j0 < G3) {
        A0 = g_h00; A1 = g_h01;
        W0 = g_wi10 + (long)j0 * D_;
        W1 = g_wi11 + (long)j0 * D_;
    } else {
        A0 = g_h10; A1 = g_h11;
        W0 = g_wh10 + (long)(j0 - G3) * D_;
        W1 = g_wh11 + (long)(j0 - G3) * D_;
    }
    hgemm_64x128(A0, A1, D_, W0, W1, D_,
                 g_gP1 + (long)sp * (B_ * 2 * G3) + j0, (long)(2 * G3), sp * 64, 2,
                 1, SLOT(step, 1), R * 32u, false, -1, 0);
    bump_slot(SLOT(step, 2));
}

__global__ void __launch_bounds__(256) k_combine(
    const float* __restrict__ b_ih, const float* __restrict__ b_hh,
    int layer, int zgi, int step)
{
    GD_TRIGGER();
    unsigned R = rep_now();
    if (layer == 0) {
        spin_slot(SLOT(step, 0), R * (step == 0 ? 96u : 192u));
    } else {
        spin_slot(SLOT(step, 2), R * 192u);
    }
    // layer1 resets the argmax keys (after gru0(step) gi consumed them;
    // transitively ordered: gru1 waited combine0 waited gru0-done)
    if (layer == 1 && blockIdx.x == 0 && threadIdx.x < B_)
        g_best[threadIdx.x] = 0ull;
    int idx = (blockIdx.x * 256 + threadIdx.x) * 4;
    int d = idx & (D_ - 1);
    long base = (long)(idx >> 9) * (2 * G3);
    const float* gPb = layer ? g_gP1 : g_gP0;
    float4 s0 = {0,0,0,0}, s1 = {0,0,0,0}, s2 = {0,0,0,0};
    float4 s3 = {0,0,0,0}, s4 = {0,0,0,0}, s5 = {0,0,0,0};
#pragma unroll
    for (int sp = 0; sp < 8; sp++) {
        const float* p = gPb + (long)sp * (B_ * 2 * G3) + base;
        if (!zgi) {
            add4(s0, *(const float4*)(p + d));
            add4(s1, *(const float4*)(p + 512 + d));
            add4(s2, *(const float4*)(p + 1024 + d));
        }
        add4(s3, *(const float4*)(p + 1536 + d));
        add4(s4, *(const float4*)(p + 2048 + d));
        add4(s5, *(const float4*)(p + 2560 + d));
    }
    float4 bir = *(const float4*)(b_ih + d);
    float4 biz = *(const float4*)(b_ih + 512 + d);
    float4 bin = *(const float4*)(b_ih + 1024 + d);
    float4 bhr = *(const float4*)(b_hh + d);
    float4 bhz = *(const float4*)(b_hh + 512 + d);
    float4 bhn = *(const float4*)(b_hh + 1024 + d);

    float* hf = layer ? g_h1f : g_h0f;
    float4 hp = *(const float4*)(hf + idx);
    float gi[4] = {s0.x + bir.x, s0.y + bir.y, s0.z + bir.z, s0.w + bir.w};
    float gz[4] = {s1.x + biz.x, s1.y + biz.y, s1.z + biz.z, s1.w + biz.w};
    float gn[4] = {s2.x + bin.x, s2.y + bin.y, s2.z + bin.z, s2.w + bin.w};
    float hr[4] = {s3.x + bhr.x, s3.y + bhr.y, s3.z + bhr.z, s3.w + bhr.w};
    float hz[4] = {s4.x + bhz.x, s4.y + bhz.y, s4.z + bhz.z, s4.w + bhz.w};
    float hn4[4] = {s5.x + bhn.x, s5.y + bhn.y, s5.z + bhn.z, s5.w + bhn.w};
    float hpv[4] = {hp.x, hp.y, hp.z, hp.w};
    float out4[4];
#pragma unroll
    for (int i = 0; i < 4; i++) {
        float r = 1.f / (1.f + expf(-(gi[i] + hr[i])));
        float z = 1.f / (1.f + expf(-(gz[i] + hz[i])));
        float n = tanhf(gn[i] + r * hn4[i]);
        out4[i] = n + z * (hpv[i] - n);
    }
    float4 ov = {out4[0], out4[1], out4[2], out4[3]};
    *(float4*)(hf + idx) = ov;
    if (layer) split_store4(ov, g_h10, g_h11, idx);
    else       split_store4(ov, g_h00, g_h01, idx);
    bump_slot(SLOT(step, layer ? 3 : 1));
}

__global__ void __launch_bounds__(256) k_logits(float* __restrict__ out, int step,
                                                int do_cand)
{
    GD_TRIGGER();
    unsigned R = rep_now();
    int tile = blockIdx.x;
    int n0 = tile * 128;
    hgemm_64x128(g_h10, g_h11, D_,
                 g_wo0 + (long)n0 * D_, g_wo1 + (long)n0 * D_, D_,
                 out + (long)step * V_ + n0, LDOUT, 0, 16,
                 1, SLOT(step, 3), R * 32u, true, do_cand ? tile : -1, n0);
    bump_slot(SLOT(step, 4));
}

// ------------------------------ launch --------------------------------------
template <typename F, typename... Args>
static void launch_pdl(F f, dim3 g, dim3 b, size_t smem, Args... args)
{
    cudaLaunchConfig_t cfg = {};
    cfg.gridDim = g;
    cfg.blockDim = b;
    cfg.dynamicSmemBytes = smem;
    cfg.stream = 0;
    cudaLaunchAttribute at[1];
    at[0].id = cudaLaunchAttributeProgrammaticStreamSerialization;
    at[0].val.programmaticStreamSerializationAllowed = 1;
    cfg.attrs = at;
    cfg.numAttrs = 1;
    (void)cudaLaunchKernelEx(&cfg, f, args...);
}

extern "C" void kernel_launch(void* const* d_in, const int* in_sizes, int n_in,
                              void* d_out, int out_size)
{
    const float* hid  = (const float*)d_in[0];
    const float* ipw  = (const float*)d_in[1];
    const float* ipb  = (const float*)d_in[2];
    const float* wih0 = (const float*)d_in[3];
    const float* whh0 = (const float*)d_in[4];
    const float* bih0 = (const float*)d_in[5];
    const float* bhh0 = (const float*)d_in[6];
    const float* wih1 = (const float*)d_in[7];
    const float* whh1 = (const float*)d_in[8];
    const float* bih1 = (const float*)d_in[9];
    const float* bhh1 = (const float*)d_in[10];
    const float* emb  = (const float*)d_in[11];
    const float* outw = (const float*)d_in[12];
    float* out = (float*)d_out;

    static cudaStream_t s2 = nullptr;
    static cudaEvent_t evFork = nullptr, evWo = nullptr;
    if (s2 == nullptr) {
        cudaStreamCreateWithFlags(&s2, cudaStreamNonBlocking);
        cudaEventCreateWithFlags(&evFork, cudaEventDisableTiming);
        cudaEventCreateWithFlags(&evWo, cudaEventDisableTiming);
        cudaFuncSetAttribute(k_inproj, cudaFuncAttributeMaxDynamicSharedMemorySize, DYN_SMEM);
        cudaFuncSetAttribute(k_gru0,   cudaFuncAttributeMaxDynamicSharedMemorySize, DYN_SMEM);
        cudaFuncSetAttribute(k_gru1,   cudaFuncAttributeMaxDynamicSharedMemorySize, DYN_SMEM);
        cudaFuncSetAttribute(k_logits, cudaFuncAttributeMaxDynamicSharedMemorySize, DYN_SMEM);
    }

    // fork: throttled out_w split co-runs with the pre-logits chain
    cudaEventRecord(evFork, 0);
    cudaStreamWaitEvent(s2, evFork, 0);
    k_split_wo<<<96, 256, 0, s2>>>(outw);
    cudaEventRecord(evWo, s2);

    k_split_rest<<<5376, 256>>>(wih0, whh0, wih1, whh1, ipw, hid);
    launch_pdl(k_inproj, dim3(4, 16), dim3(256), (size_t)DYN_SMEM);
    launch_pdl(k_reduce, dim3(32), dim3(256), (size_t)0, ipb);

    for (int t = 0; t < 4; t++) {
        launch_pdl(k_gru0, dim3(t == 0 ? 12 : 24, 8), dim3(256),
                   (size_t)DYN_SMEM, t, emb);
        launch_pdl(k_combine, dim3(32), dim3(256), (size_t)0,
                   bih0, bhh0, 0, t == 0 ? 1 : 0, t);
        launch_pdl(k_gru1, dim3(24, 8), dim3(256), (size_t)DYN_SMEM, t);
        launch_pdl(k_combine, dim3(32), dim3(256), (size_t)0, bih1, bhh1, 1, 0, t);
        if (t == 0) cudaStreamWaitEvent(0, evWo, 0);
        launch_pdl(k_logits, dim3(NTILES_V), dim3(256), (size_t)DYN_SMEM,
                   out, t, t < 3 ? 1 : 0);
    }
}

// round 17
// speedup vs baseline: 1.0983x; 1.0983x over previous
#include <cuda_runtime.h>
#include <cuda_bf16.h>
#include <math.h>
#include <stdint.h>

// ReDrafterHead via mma.sync bf16 (HMMA), multi-kernel + PDL.
// B=64, D=512, H=4096, V=32000, K=4. Exact 2-way bf16 split, 3 cross products
// (a0w0+a0w1+a1w0), fp32 accum.
// R17 = R13 + combine/reduce fused into the GEMM kernels as last-32-block
// epilogues (intra-kernel ticket + short spin; no cross-kernel spins).
// Chain: inproj(+reduce) -> [gru0(+combine0) -> gru1(+combine1) -> logits] x4.

#define B_ 64
#define D_ 512
#define H_ 4096
#define V_ 32000
#define G3 1536
#define LDOUT 128000L
#define NTILES_V 250

#define STAGE_BYTES 30720        // A0(5120)+A1(5120)+W0(10240)+W1(10240)
#define NSTAGE 3
#define DYN_SMEM (STAGE_BYTES * NSTAGE)

#define GD_TRIGGER() asm volatile("griddepcontrol.launch_dependents;" ::: "memory")
#define GD_WAIT()    asm volatile("griddepcontrol.wait;" ::: "memory")

// ------------------------------ device scratch ------------------------------
__device__ __align__(128) __nv_bfloat16 g_wo0[V_ * D_],  g_wo1[V_ * D_];
__device__ __align__(128) __nv_bfloat16 g_wi00[G3 * D_], g_wi01[G3 * D_];
__device__ __align__(128) __nv_bfloat16 g_wh00[G3 * D_], g_wh01[G3 * D_];
__device__ __align__(128) __nv_bfloat16 g_wi10[G3 * D_], g_wi11[G3 * D_];
__device__ __align__(128) __nv_bfloat16 g_wh10[G3 * D_], g_wh11[G3 * D_];
__device__ __align__(128) __nv_bfloat16 g_ip0[D_ * H_],  g_ip1[D_ * H_];
__device__ __align__(128) __nv_bfloat16 g_hid0[B_ * H_], g_hid1[B_ * H_];
__device__ __align__(128) __nv_bfloat16 g_h00[B_ * D_],  g_h01[B_ * D_];
__device__ __align__(128) __nv_bfloat16 g_h10[B_ * D_],  g_h11[B_ * D_];
__device__ __align__(128) float g_h0f[B_ * D_];
__device__ __align__(128) float g_h1f[B_ * D_];
__device__ __align__(128) float g_ipart[16 * B_ * D_];
__device__ __align__(128) float g_gP0[8 * B_ * 2 * G3];   // layer0 gate partials
__device__ __align__(128) float g_gP1[8 * B_ * 2 * G3];   // layer1 gate partials
__device__ unsigned long long g_best[B_];                 // packed argmax keys
__device__ unsigned g_tk[3];     // monotonic tickets: 0=inproj, 1=gru0, 2=gru1

// ------------------------------ helpers -------------------------------------
__device__ __forceinline__ uint32_t smem_u32(const void* p) {
    uint32_t a;
    asm("{ .reg .u64 t; cvta.to.shared.u64 t, %1; cvt.u32.u64 %0, t; }" : "=r"(a) : "l"(p));
    return a;
}
__device__ __forceinline__ void cp16(uint32_t dst, const void* src) {
    asm volatile("cp.async.cg.shared.global [%0], [%1], 16;" :: "r"(dst), "l"(src));
}
__device__ __forceinline__ void ldsm4(uint32_t* r, uint32_t a) {
    asm volatile("ldmatrix.sync.aligned.m8n8.x4.shared.b16 {%0,%1,%2,%3}, [%4];"
                 : "=r"(r[0]), "=r"(r[1]), "=r"(r[2]), "=r"(r[3]) : "r"(a));
}
__device__ __forceinline__ void mma16816(float* c, const uint32_t* a,
                                         uint32_t b0, uint32_t b1) {
    asm volatile(
        "mma.sync.aligned.m16n8k16.row.col.f32.bf16.bf16.f32 "
        "{%0,%1,%2,%3}, {%4,%5,%6,%7}, {%8,%9}, {%0,%1,%2,%3};"
        : "+f"(c[0]), "+f"(c[1]), "+f"(c[2]), "+f"(c[3])
        : "r"(a[0]), "r"(a[1]), "r"(a[2]), "r"(a[3]), "r"(b0), "r"(b1));
}
__device__ __forceinline__ void st2cs(float* p, float x, float y) {
    asm volatile("st.global.cs.v2.f32 [%0], {%1, %2};" :: "l"(p), "f"(x), "f"(y)
                 : "memory");
}
__device__ __forceinline__ void split_store4(float4 v, __nv_bfloat16* d0,
                                             __nv_bfloat16* d1, long o)
{
    __nv_bfloat16 h0 = __float2bfloat16(v.x), h1 = __float2bfloat16(v.y);
    __nv_bfloat16 h2 = __float2bfloat16(v.z), h3 = __float2bfloat16(v.w);
    __nv_bfloat162 ha, hb, la, lb;
    ha.x = h0; ha.y = h1; hb.x = h2; hb.y = h3;
    la.x = __float2bfloat16(v.x - __bfloat162float(h0));
    la.y = __float2bfloat16(v.y - __bfloat162float(h1));
    lb.x = __float2bfloat16(v.z - __bfloat162float(h2));
    lb.y = __float2bfloat16(v.w - __bfloat162float(h3));
    *(__nv_bfloat162*)(d0 + o)     = ha;
    *(__nv_bfloat162*)(d0 + o + 2) = hb;
    *(__nv_bfloat162*)(d1 + o)     = la;
    *(__nv_bfloat162*)(d1 + o + 2) = lb;
}
__device__ __forceinline__ void add4(float4& a, float4 b) {
    a.x += b.x; a.y += b.y; a.z += b.z; a.w += b.w;
}

// Ticket election: block arrives (release), last `nsl` arrivals of THIS launch
// are elected; they spin (on their own grid only) until all `total` arrive.
// Monotonic counter + modular position => replay-safe (each launch adds total).
__device__ __forceinline__ int ticket_elect(unsigned* ctr, unsigned total,
                                            unsigned nsl)
{
    __shared__ unsigned s_ret;
    __threadfence();
    __syncthreads();
    if (threadIdx.x == 0) s_ret = atomicAdd(ctr, 1u);
    __syncthreads();
    unsigned ret = s_ret;
    unsigned pos = ret % total;
    if (pos < total - nsl) return -1;
    unsigned target = ret - pos + total;
    if (threadIdx.x == 0) {
        unsigned r;
        for (;;) {
            asm volatile("ld.global.acquire.gpu.u32 %0, [%1];" : "=r"(r) : "l"(ctr));
            if ((int)(r - target) >= 0) break;
            __nanosleep(32);
        }
    }
    __syncthreads();
    return (int)(pos - (total - nsl));
}

// GRU combine for one slice of 1024 elements (256 threads x float4)
__device__ void combine_slice(int slice, const float* __restrict__ gPb,
                              const float* __restrict__ b_ih,
                              const float* __restrict__ b_hh,
                              int layer, int zgi)
{
    int idx = (slice * 256 + threadIdx.x) * 4;
    int d = idx & (D_ - 1);
    long base = (long)(idx >> 9) * (2 * G3);
    float4 s0 = {0,0,0,0}, s1 = {0,0,0,0}, s2 = {0,0,0,0};
    float4 s3 = {0,0,0,0}, s4 = {0,0,0,0}, s5 = {0,0,0,0};
#pragma unroll
    for (int sp = 0; sp < 8; sp++) {
        const float* p = gPb + (long)sp * (B_ * 2 * G3) + base;
        if (!zgi) {
            add4(s0, *(const float4*)(p + d));
            add4(s1, *(const float4*)(p + 512 + d));
            add4(s2, *(const float4*)(p + 1024 + d));
        }
        add4(s3, *(const float4*)(p + 1536 + d));
        add4(s4, *(const float4*)(p + 2048 + d));
        add4(s5, *(const float4*)(p + 2560 + d));
    }
    float4 bir = *(const float4*)(b_ih + d);
    float4 biz = *(const float4*)(b_ih + 512 + d);
    float4 bin = *(const float4*)(b_ih + 1024 + d);
    float4 bhr = *(const float4*)(b_hh + d);
    float4 bhz = *(const float4*)(b_hh + 512 + d);
    float4 bhn = *(const float4*)(b_hh + 1024 + d);

    float* hf = layer ? g_h1f : g_h0f;
    float4 hp = *(const float4*)(hf + idx);
    float gi[4] = {s0.x + bir.x, s0.y + bir.y, s0.z + bir.z, s0.w + bir.w};
    float gz[4] = {s1.x + biz.x, s1.y + biz.y, s1.z + biz.z, s1.w + biz.w};
    float gn[4] = {s2.x + bin.x, s2.y + bin.y, s2.z + bin.z, s2.w + bin.w};
    float hr[4] = {s3.x + bhr.x, s3.y + bhr.y, s3.z + bhr.z, s3.w + bhr.w};
    float hz[4] = {s4.x + bhz.x, s4.y + bhz.y, s4.z + bhz.z, s4.w + bhz.w};
    float hn4[4] = {s5.x + bhn.x, s5.y + bhn.y, s5.z + bhn.z, s5.w + bhn.w};
    float hpv[4] = {hp.x, hp.y, hp.z, hp.w};
    float out4[4];
#pragma unroll
    for (int i = 0; i < 4; i++) {
        float r = 1.f / (1.f + expf(-(gi[i] + hr[i])));
        float z = 1.f / (1.f + expf(-(gz[i] + hz[i])));
        float n = tanhf(gn[i] + r * hn4[i]);
        out4[i] = n + z * (hpv[i] - n);
    }
    float4 ov = {out4[0], out4[1], out4[2], out4[3]};
    *(float4*)(hf + idx) = ov;
    if (layer) split_store4(ov, g_h10, g_h11, idx);
    else       split_store4(ov, g_h00, g_h01, idx);
}

// file-scope stage loaders (use threadIdx.x)
#define LOAD_A_G(sb_, A0p, A1p, lda, kb) do {                                  \
    _Pragma("unroll")                                                          \
    for (int j_ = 0; j_ < 2; j_++) {                                           \
        int q_ = threadIdx.x + j_ * 256;                                       \
        int sp_ = q_ >> 8, rem_ = q_ & 255;                                    \
        int row_ = rem_ >> 2, kc_ = rem_ & 3;                                  \
        cp16((sb_) + (uint32_t)sp_ * 5120u + (uint32_t)row_ * 80u              \
                 + (uint32_t)kc_ * 16u,                                        \
             (sp_ ? (A1p) : (A0p)) + (long)row_ * (lda) + (kb) + kc_ * 8);     \
    }                                                                          \
} while (0)

#define LOAD_W_G(sb_, W0p, W1p, ldw, kb) do {                                  \
    _Pragma("unroll")                                                          \
    for (int j_ = 0; j_ < 4; j_++) {                                           \
        int qq_ = threadIdx.x + j_ * 256;                                      \
        int sp_ = qq_ >> 9, rem_ = qq_ & 511;                                  \
        int row_ = rem_ >> 2, kc_ = rem_ & 3;                                  \
        cp16((sb_) + 10240u + (uint32_t)sp_ * 10240u                           \
                 + (uint32_t)row_ * 80u + (uint32_t)kc_ * 16u,                 \
             (sp_ ? (W1p) : (W0p)) + (long)row_ * (ldw) + (kb) + kc_ * 8);     \
    }                                                                          \
} while (0)

#define COMMIT_G() asm volatile("cp.async.commit_group;" ::: "memory")

// 32-K-chunk compute on the 80B-padded stage layout
__device__ __forceinline__ void compute32(uint32_t sb, float acc[2][4][4],
                                          int lane, int wm, int wn)
{
    uint32_t A0b = sb, A1b = sb + 5120u, W0b = sb + 10240u, W1b = sb + 20480u;
    const int l8 = lane & 7, sel = lane >> 3;
    const uint32_t a_row = (uint32_t)((sel & 1) * 8 + l8);
    const uint32_t a_k8  = (uint32_t)((sel >> 1) * 8);
    const uint32_t b_n   = (uint32_t)(((sel >> 1) ? 8 : 0) + l8);
    const uint32_t b_k8  = (uint32_t)((sel & 1) * 8);
#pragma unroll
    for (int ko = 0; ko < 32; ko += 16) {
        uint32_t a0r[2][4], a1r[2][4], w0r[2][4], w1r[2][4];
#pragma unroll
        for (int mt = 0; mt < 2; mt++) {
            uint32_t ar = (uint32_t)(wm + mt * 16 + a_row) * 80u + (ko + a_k8) * 2u;
            ldsm4(a0r[mt], A0b + ar);
            ldsm4(a1r[mt], A1b + ar);
        }
#pragma unroll
        for (int np = 0; np < 2; np++) {
            uint32_t br = (uint32_t)(wn + np * 16 + b_n) * 80u + (ko + b_k8) * 2u;
            ldsm4(w0r[np], W0b + br);
            ldsm4(w1r[np], W1b + br);
        }
#pragma unroll
        for (int mt = 0; mt < 2; mt++)
#pragma unroll
            for (int nt = 0; nt < 4; nt++)
                mma16816(acc[mt][nt], a0r[mt],
                         w0r[nt >> 1][(nt & 1) * 2], w0r[nt >> 1][(nt & 1) * 2 + 1]);
#pragma unroll
        for (int mt = 0; mt < 2; mt++)
#pragma unroll
            for (int nt = 0; nt < 4; nt++)
                mma16816(acc[mt][nt], a0r[mt],
                         w1r[nt >> 1][(nt & 1) * 2], w1r[nt >> 1][(nt & 1) * 2 + 1]);
#pragma unroll
        for (int mt = 0; mt < 2; mt++)
#pragma unroll
            for (int nt = 0; nt < 4; nt++)
                mma16816(acc[mt][nt], a1r[mt],
                         w0r[nt >> 1][(nt & 1) * 2], w0r[nt >> 1][(nt & 1) * 2 + 1]);
    }
}

__device__ __forceinline__ void store_acc(float acc[2][4][4], float* C, long ldc,
                                          int lane, int wm, int wn)
{
    const int row0 = wm + (lane >> 2);
    const int col0 = wn + (lane & 3) * 2;
#pragma unroll
    for (int mt = 0; mt < 2; mt++)
#pragma unroll
        for (int nt = 0; nt < 4; nt++) {
            float* p = C + (long)(row0 + mt * 16) * ldc + col0 + nt * 8;
            *(float2*)p = make_float2(acc[mt][nt][0], acc[mt][nt][1]);
            float* p2 = p + 8 * ldc;
            *(float2*)p2 = make_float2(acc[mt][nt][2], acc[mt][nt][3]);
        }
}

// ------------------------------ staged GEMM ---------------------------------
// pdl: 1 = W stages 0/1 prefetched BEFORE wait; 2 = wait first.
__device__ __forceinline__ void hgemm_64x128(
    const __nv_bfloat16* __restrict__ A0, const __nv_bfloat16* __restrict__ A1, int lda,
    const __nv_bfloat16* __restrict__ W0, const __nv_bfloat16* __restrict__ W1, int ldw,
    float* __restrict__ C, long ldc, int klo, int nchunk,
    int pdl, bool streamc, int tile, int n0)
{
    extern __shared__ __align__(16) char dynsm[];
    __shared__ float sv[4][64];
    __shared__ int   si[4][64];
    uint32_t sbase = smem_u32(dynsm);
    const int t = threadIdx.x;
    const int lane = t & 31, wid = t >> 5;
    const int wm = (wid & 1) * 32, wn = (wid >> 1) * 32;

    float acc[2][4][4];
#pragma unroll
    for (int i = 0; i < 2; i++)
#pragma unroll
        for (int j = 0; j < 4; j++)
#pragma unroll
            for (int q = 0; q < 4; q++) acc[i][j][q] = 0.f;

    uint32_t sb0 = sbase, sb1 = sbase + STAGE_BYTES;
    if (pdl == 1) {
        LOAD_W_G(sb0, W0, W1, ldw, klo);
        if (nchunk > 1) LOAD_W_G(sb1, W0, W1, ldw, klo + 32);
        GD_WAIT();
        LOAD_A_G(sb0, A0, A1, lda, klo);
        COMMIT_G();                       // group0 = {W0, W1, A0}
        if (nchunk > 1) { LOAD_A_G(sb1, A0, A1, lda, klo + 32); COMMIT_G(); }
    } else {
        if (pdl == 2) GD_WAIT();
        LOAD_A_G(sb0, A0, A1, lda, klo); LOAD_W_G(sb0, W0, W1, ldw, klo); COMMIT_G();
        if (nchunk > 1) {
            LOAD_A_G(sb1, A0, A1, lda, klo + 32);
            LOAD_W_G(sb1, W0, W1, ldw, klo + 32);
            COMMIT_G();
        }
    }

    for (int s = 0; s < nchunk; s++) {
        if (s + 1 < nchunk) asm volatile("cp.async.wait_group 1;" ::: "memory");
        else                asm volatile("cp.async.wait_group 0;" ::: "memory");
        __syncthreads();
        if (s + 2 < nchunk) {
            int kb2 = klo + (s + 2) * 32;
            uint32_t sb2 = sbase + (uint32_t)((s + 2) % NSTAGE) * STAGE_BYTES;
            LOAD_A_G(sb2, A0, A1, lda, kb2);
            LOAD_W_G(sb2, W0, W1, ldw, kb2);
            COMMIT_G();
        }
        compute32(sbase + (uint32_t)(s % NSTAGE) * STAGE_BYTES, acc, lane, wm, wn);
        __syncthreads();
    }

    if (!streamc) {
        store_acc(acc, C, ldc, lane, wm, wn);
    } else {
        const int row0 = wm + (lane >> 2);
        const int col0 = wn + (lane & 3) * 2;
#pragma unroll
        for (int mt = 0; mt < 2; mt++)
#pragma unroll
            for (int nt = 0; nt < 4; nt++) {
                float* p = C + (long)(row0 + mt * 16) * ldc + col0 + nt * 8;
                st2cs(p,  acc[mt][nt][0], acc[mt][nt][1]);
                st2cs(p + 8 * ldc, acc[mt][nt][2], acc[mt][nt][3]);
            }
    }

    if (tile >= 0) {
        // per-row argmax over this tile's 128 cols -> packed atomic key
#pragma unroll
        for (int mt = 0; mt < 2; mt++)
#pragma unroll
            for (int h = 0; h < 2; h++) {
                float bv = -3.4e38f;
                int bi = 0x7FFFFFFF;
#pragma unroll
                for (int nt = 0; nt < 4; nt++) {
                    int cc = wn + nt * 8 + (lane & 3) * 2;
                    float v0 = acc[mt][nt][h * 2];
                    float v1 = acc[mt][nt][h * 2 + 1];
                    if (v0 > bv || (v0 == bv && cc < bi))     { bv = v0; bi = cc; }
                    if (v1 > bv || (v1 == bv && cc + 1 < bi)) { bv = v1; bi = cc + 1; }
                }
#pragma unroll
                for (int off = 1; off <= 2; off <<= 1) {
                    float ov = __shfl_xor_sync(0xFFFFFFFF, bv, off);
                    int   oi = __shfl_xor_sync(0xFFFFFFFF, bi, off);
                    if (ov > bv || (ov == bv && oi < bi)) { bv = ov; bi = oi; }
                }
                if ((lane & 3) == 0) {
                    int r = wm + mt * 16 + (lane >> 2) + h * 8;
                    sv[wid >> 1][r] = bv;
                    si[wid >> 1][r] = bi;
                }
            }
        __syncthreads();
        if (t < 64) {
            float bv = sv[0][t];
            int bi = si[0][t];
#pragma unroll
            for (int g = 1; g < 4; g++) {
                float v = sv[g][t];
                int i = si[g][t];
                if (v > bv || (v == bv && i < bi)) { bv = v; bi = i; }
            }
            int gidx = n0 + bi;
            uint32_t fu = __float_as_uint(bv);
            fu = (fu & 0x80000000u) ? ~fu : (fu | 0x80000000u);
            unsigned long long key = ((unsigned long long)fu << 32)
                                   | (unsigned long long)(0xFFFFFFFFu - (uint32_t)gidx);
            atomicMax(&g_best[t], key);
        }
        __syncthreads();
    }
}

// ------------------------------ kernels -------------------------------------
__global__ void __launch_bounds__(256) k_split_wo(const float* __restrict__ outw)
{
    const long G4 = (long)V_ * D_ / 4;
    const long stride = 96L * 256L;
    for (long g = (long)blockIdx.x * 256 + threadIdx.x; g < G4; g += stride * 8) {
        float4 v[8];
#pragma unroll
        for (int j = 0; j < 8; j++) {
            long q = g + (long)j * stride;
            if (q < G4) v[j] = *((const float4*)outw + q);
        }
#pragma unroll
        for (int j = 0; j < 8; j++) {
            long q = g + (long)j * stride;
            if (q < G4) split_store4(v[j], g_wo0, g_wo1, q * 4);
        }
    }
}

#define R1 786432L
#define R2 1572864L
#define R3 2359296L
#define R4 3145728L
#define R5 5242880L
#define R6 5505024L
__global__ void __launch_bounds__(256) k_split_rest(
    const float* __restrict__ wih0, const float* __restrict__ whh0,
    const float* __restrict__ wih1, const float* __restrict__ whh1,
    const float* __restrict__ ipw,  const float* __restrict__ hid)
{
    long e = ((long)blockIdx.x * 256 + threadIdx.x) * 4;
    if (e >= R6) return;
    const float* s;
    __nv_bfloat16 *d0, *d1;
    long o;
    if (e < R1)      { s = wih0; d0 = g_wi00; d1 = g_wi01; o = e; }
    else if (e < R2) { s = whh0; d0 = g_wh00; d1 = g_wh01; o = e - R1; }
    else if (e < R3) { s = wih1; d0 = g_wi10; d1 = g_wi11; o = e - R2; }
    else if (e < R4) { s = whh1; d0 = g_wh10; d1 = g_wh11; o = e - R3; }
    else if (e < R5) { s = ipw;  d0 = g_ip0;  d1 = g_ip1;  o = e - R4; }
    else             { s = hid;  d0 = g_hid0; d1 = g_hid1; o = e - R5; }
    float4 v = *(const float4*)(s + o);
    split_store4(v, d0, d1, o);
}

// inproj GEMM + fused reduce/init epilogue (last 32 of 64 blocks)
__global__ void __launch_bounds__(256) k_inproj(const float* __restrict__ bias)
{
    GD_TRIGGER();
    int n0 = blockIdx.x * 128;
    int sp = blockIdx.y;
    hgemm_64x128(g_hid0, g_hid1, H_,
                 g_ip0 + (long)n0 * H_, g_ip1 + (long)n0 * H_, H_,
                 g_ipart + (long)sp * (B_ * D_) + n0, (long)D_, sp * 256, 8,
                 2, false, -1, 0);
    int slice = ticket_elect(&g_tk[0], 64u, 32u);
    if (slice < 0) return;
    int idx = (slice * 256 + threadIdx.x) * 4;
    int d = idx & (D_ - 1);
    float4 s = *(const float4*)(bias + d);
#pragma unroll
    for (int sp2 = 0; sp2 < 16; sp2++)
        add4(s, *(const float4*)(g_ipart + sp2 * (B_ * D_) + idx));
    *(float4*)(g_h0f + idx) = s;
    *(float4*)(g_h1f + idx) = s;
    split_store4(s, g_h00, g_h01, idx);
    split_store4(s, g_h10, g_h11, idx);
}

// Layer0 GRU + fused combine0 (last 32 of 192 blocks).
// Grid always (24,8). tiles 0-11 = gi: step 0 skips the GEMM (x = 0);
// steps 1..3 gather embed[argmax] in the prologue. tiles 12-23 = gh.
__global__ void __launch_bounds__(256) k_gru0(int step, const float* __restrict__ emb,
                                              const float* __restrict__ b_ih,
                                              const float* __restrict__ b_hh)
{
    GD_TRIGGER();
    int tile = blockIdx.x;
    int sp = blockIdx.y;
    int j0 = tile * 128;
    int klo = sp * 64;

    if (tile >= 12) {
        hgemm_64x128(g_h00, g_h01, D_,
                     g_wh00 + (long)(j0 - G3) * D_, g_wh01 + (long)(j0 - G3) * D_, D_,
                     g_gP0 + (long)sp * (B_ * 2 * G3) + j0, (long)(2 * G3), klo, 2,
                     1, false, -1, 0);
    } else if (step > 0) {
        // gi half: A = embed[argmax from g_best] gathered into smem stage
        extern __shared__ __align__(16) char dynsm[];
        __shared__ int win[64];
        uint32_t sbase = smem_u32(dynsm);
        const int t = threadIdx.x, lane = t & 31, wid = t >> 5;
        const int wm = (wid & 1) * 32, wn = (wid >> 1) * 32;
        const __nv_bfloat16* W0 = g_wi00 + (long)j0 * D_;
        const __nv_bfloat16* W1 = g_wi01 + (long)j0 * D_;
        uint32_t sb0 = sbase, sb1 = sbase + STAGE_BYTES;

        LOAD_W_G(sb0, W0, W1, D_, klo); COMMIT_G();        // group0
        LOAD_W_G(sb1, W0, W1, D_, klo + 32); COMMIT_G();   // group1
        GD_WAIT();

        if (t < 64) {
            unsigned long long v = g_best[t];
            win[t] = (int)(0xFFFFFFFFu - (uint32_t)(v & 0xFFFFFFFFull));
        }
        __syncthreads();
        {
            int r = t >> 2, c0 = (t & 3) * 16;
            const float* erow = emb + (long)win[r] * D_ + klo;
#pragma unroll
            for (int cc = 0; cc < 16; cc += 4) {
                float4 v4 = *(const float4*)(erow + c0 + cc);
                float vv[4] = {v4.x, v4.y, v4.z, v4.w};
#pragma unroll
                for (int i = 0; i < 4; i++) {
                    int k = c0 + cc + i;
                    uint32_t sb = (k >= 32) ? sb1 : sb0;
                    int kk = k & 31;
                    uint32_t off = (uint32_t)r * 80u + (uint32_t)(kk >> 3) * 16u
                                 + (uint32_t)(kk & 7) * 2u;
                    __nv_bfloat16 hi = __float2bfloat16(vv[i]);
                    __nv_bfloat16 lo = __float2bfloat16(vv[i] - __bfloat162float(hi));
                    *(__nv_bfloat16*)(dynsm + (sb - sbase) + off) = hi;
                    *(__nv_bfloat16*)(dynsm + (sb - sbase) + 5120u + off) = lo;
                }
            }
        }

        float acc[2][4][4];
#pragma unroll
        for (int i = 0; i < 2; i++)
#pragma unroll
            for (int j = 0; j < 4; j++)
#pragma unroll
                for (int q = 0; q < 4; q++) acc[i][j][q] = 0.f;

        asm volatile("cp.async.wait_group 1;" ::: "memory");
        __syncthreads();                 // A smem stores + W group0 visible
        compute32(sb0, acc, lane, wm, wn);
        asm volatile("cp.async.wait_group 0;" ::: "memory");
        __syncthreads();
        compute32(sb1, acc, lane, wm, wn);

        store_acc(acc, g_gP0 + (long)sp * (B_ * 2 * G3) + j0, (long)(2 * G3),
                  lane, wm, wn);
    } else {
        // step 0 gi: x = 0, nothing to compute; just observe the dependency
        GD_WAIT();
    }

    int slice = ticket_elect(&g_tk[1], 192u, 32u);
    if (slice < 0) return;
    combine_slice(slice, g_gP0, b_ih, b_hh, 0, step == 0 ? 1 : 0);
}

// Layer1 GRU + fused combine1 (+ argmax-key reset) epilogue
__global__ void __launch_bounds__(256) k_gru1(const float* __restrict__ b_ih,
                                              const float* __restrict__ b_hh)
{
    GD_TRIGGER();
    int tile = blockIdx.x;
    int sp = blockIdx.y;
    int j0 = tile * 128;
    const __nv_bfloat16 *A0, *A1, *W0, *W1;
    if (j0 < G3) {
        A0 = g_h00; A1 = g_h01;
        W0 = g_wi10 + (long)j0 * D_;
        W1 = g_wi11 + (long)j0 * D_;
    } else {
        A0 = g_h10; A1 = g_h11;
        W0 = g_wh10 + (long)(j0 - G3) * D_;
        W1 = g_wh11 + (long)(j0 - G3) * D_;
    }
    hgemm_64x128(A0, A1, D_, W0, W1, D_,
                 g_gP1 + (long)sp * (B_ * 2 * G3) + j0, (long)(2 * G3), sp * 64, 2,
                 1, false, -1, 0);
    int slice = ticket_elect(&g_tk[2], 192u, 32u);
    if (slice < 0) return;
    // reset argmax keys (gi of this step consumed them before gru1 started)
    if (slice == 0 && threadIdx.x < B_) g_best[threadIdx.x] = 0ull;
    combine_slice(slice, g_gP1, b_ih, b_hh, 1, 0);
}

__global__ void __launch_bounds__(256) k_logits(float* __restrict__ out, int step,
                                                int do_cand)
{
    GD_TRIGGER();
    int tile = blockIdx.x;
    int n0 = tile * 128;
    hgemm_64x128(g_h10, g_h11, D_,
                 g_wo0 + (long)n0 * D_, g_wo1 + (long)n0 * D_, D_,
                 out + (long)step * V_ + n0, LDOUT, 0, 16,
                 1, true, do_cand ? tile : -1, n0);
}

// ------------------------------ launch --------------------------------------
template <typename F, typename... Args>
static void launch_pdl(F f, dim3 g, dim3 b, size_t smem, Args... args)
{
    cudaLaunchConfig_t cfg = {};
    cfg.gridDim = g;
    cfg.blockDim = b;
    cfg.dynamicSmemBytes = smem;
    cfg.stream = 0;
    cudaLaunchAttribute at[1];
    at[0].id = cudaLaunchAttributeProgrammaticStreamSerialization;
    at[0].val.programmaticStreamSerializationAllowed = 1;
    cfg.attrs = at;
    cfg.numAttrs = 1;
    (void)cudaLaunchKernelEx(&cfg, f, args...);
}

extern "C" void kernel_launch(void* const* d_in, const int* in_sizes, int n_in,
                              void* d_out, int out_size)
{
    const float* hid  = (const float*)d_in[0];
    const float* ipw  = (const float*)d_in[1];
    const float* ipb  = (const float*)d_in[2];
    const float* wih0 = (const float*)d_in[3];
    const float* whh0 = (const float*)d_in[4];
    const float* bih0 = (const float*)d_in[5];
    const float* bhh0 = (const float*)d_in[6];
    const float* wih1 = (const float*)d_in[7];
    const float* whh1 = (const float*)d_in[8];
    const float* bih1 = (const float*)d_in[9];
    const float* bhh1 = (const float*)d_in[10];
    const float* emb  = (const float*)d_in[11];
    const float* outw = (const float*)d_in[12];
    float* out = (float*)d_out;

    static cudaStream_t s2 = nullptr;
    static cudaEvent_t evFork = nullptr, evWo = nullptr;
    if (s2 == nullptr) {
        cudaStreamCreateWithFlags(&s2, cudaStreamNonBlocking);
        cudaEventCreateWithFlags(&evFork, cudaEventDisableTiming);
        cudaEventCreateWithFlags(&evWo, cudaEventDisableTiming);
        cudaFuncSetAttribute(k_inproj, cudaFuncAttributeMaxDynamicSharedMemorySize, DYN_SMEM);
        cudaFuncSetAttribute(k_gru0,   cudaFuncAttributeMaxDynamicSharedMemorySize, DYN_SMEM);
        cudaFuncSetAttribute(k_gru1,   cudaFuncAttributeMaxDynamicSharedMemorySize, DYN_SMEM);
        cudaFuncSetAttribute(k_logits, cudaFuncAttributeMaxDynamicSharedMemorySize, DYN_SMEM);
    }

    // fork: throttled out_w split co-runs with the pre-logits chain
    cudaEventRecord(evFork, 0);
    cudaStreamWaitEvent(s2, evFork, 0);
    k_split_wo<<<96, 256, 0, s2>>>(outw);
    cudaEventRecord(evWo, s2);

    k_split_rest<<<5376, 256>>>(wih0, whh0, wih1, whh1, ipw, hid);
    launch_pdl(k_inproj, dim3(4, 16), dim3(256), (size_t)DYN_SMEM, ipb);

    for (int t = 0; t < 4; t++) {
        launch_pdl(k_gru0, dim3(24, 8), dim3(256), (size_t)DYN_SMEM,
                   t, emb, bih0, bhh0);
        launch_pdl(k_gru1, dim3(24, 8), dim3(256), (size_t)DYN_SMEM, bih1, bhh1);
        if (t == 0) cudaStreamWaitEvent(0, evWo, 0);
        launch_pdl(k_logits, dim3(NTILES_V), dim3(256), (size_t)DYN_SMEM,
                   out, t, t < 3 ? 1 : 0);
    }
}